// round 6
// baseline (speedup 1.0000x reference)
#include <cuda_runtime.h>
#include <cuda_bf16.h>

#define WG_EPS 1e-8f
#define BLK 256
#define NWARPS (BLK / 32)

__global__ __launch_bounds__(BLK) void wasserstein_gaussian_kernel(
    const float* __restrict__ loc1,
    const float* __restrict__ scale1,
    const float* __restrict__ rot1,
    const float* __restrict__ loc2,
    const float* __restrict__ scale2,
    const float* __restrict__ rot2,
    float* __restrict__ out,
    int B)
{
    // Warp-scoped staging of the rotation matrices only.
    // Each warp owns a 288-float (32 Gaussians x 9) slice per matrix.
    __shared__ float sr1[NWARPS][288];
    __shared__ float sr2[NWARPS][288];

    const int tid   = threadIdx.x;
    const int lane  = tid & 31;
    const int w     = tid >> 5;
    const int gwarp = blockIdx.x * NWARPS + w;   // global warp id
    const int wbase = gwarp * 32;                // first Gaussian of this warp
    const int b     = wbase + lane;

    float r1[9], r2[9];

    if (wbase + 32 <= B) {
        // ---- fast path: coalesced float4 staging of this warp's rot data ----
        const float4* pr1 = (const float4*)(rot1 + 9 * wbase);  // 72 float4
        const float4* pr2 = (const float4*)(rot2 + 9 * wbase);
        float4* v1 = (float4*)sr1[w];
        float4* v2 = (float4*)sr2[w];

        v1[lane]      = pr1[lane];
        v1[lane + 32] = pr1[lane + 32];
        v2[lane]      = pr2[lane];
        v2[lane + 32] = pr2[lane + 32];
        if (lane < 8) {
            v1[lane + 64] = pr1[lane + 64];
            v2[lane + 64] = pr2[lane + 64];
        }
        __syncwarp();

#pragma unroll
        for (int i = 0; i < 9; i++) {
            r1[i] = sr1[w][9 * lane + i];   // stride 9: bank-conflict-free
            r2[i] = sr2[w][9 * lane + i];
        }
    } else {
        // ---- tail path: direct strided loads (B % 32 != 0 case) ----
        if (b >= B) return;
#pragma unroll
        for (int i = 0; i < 9; i++) {
            r1[i] = rot1[9 * b + i];
            r2[i] = rot2[9 * b + i];
        }
    }

    if (b >= B) return;

    // ---- loc / scale: direct strided loads (only 3x line amplification) ----
    float l1[3], l2[3], s1[3], s2[3];
#pragma unroll
    for (int i = 0; i < 3; i++) {
        l1[i] = loc1[3 * b + i];
        l2[i] = loc2[3 * b + i];
        s1[i] = fmaxf(scale1[3 * b + i], WG_EPS);
        s2[i] = fmaxf(scale2[3 * b + i], WG_EPS);
    }

    // ---- loc term ----
    float d0 = l1[0] - l2[0], d1 = l1[1] - l2[1], d2 = l1[2] - l2[2];
    float loc_diff2 = d0 * d0 + d1 * d1 + d2 * d2;

    // ---- cov2 = R2 diag(s2) R2^T (6 unique entries) ----
    float cov2[3][3];
#pragma unroll
    for (int i = 0; i < 3; i++) {
#pragma unroll
        for (int k = i; k < 3; k++) {
            float v = r2[3 * i + 0] * s2[0] * r2[3 * k + 0]
                    + r2[3 * i + 1] * s2[1] * r2[3 * k + 1]
                    + r2[3 * i + 2] * s2[2] * r2[3 * k + 2];
            cov2[i][k] = v;
            cov2[k][i] = v;
        }
    }
    float tr_cov2 = cov2[0][0] + cov2[1][1] + cov2[2][2];

    // ---- M = R1^T cov2 R1 ----
    float T[3][3];
#pragma unroll
    for (int j = 0; j < 3; j++)
#pragma unroll
        for (int l = 0; l < 3; l++)
            T[j][l] = cov2[j][0] * r1[0 * 3 + l]
                    + cov2[j][1] * r1[1 * 3 + l]
                    + cov2[j][2] * r1[2 * 3 + l];

    float M[3][3];
#pragma unroll
    for (int i = 0; i < 3; i++)
#pragma unroll
        for (int l = 0; l < 3; l++)
            M[i][l] = r1[0 * 3 + i] * T[0][l]
                    + r1[1 * 3 + i] * T[1][l]
                    + r1[2 * 3 + i] * T[2][l];

    // ---- E = diag(sqrt(s1)) M diag(sqrt(s1)), symmetrized + EPS*I ----
    float q0 = sqrtf(s1[0]), q1 = sqrtf(s1[1]), q2 = sqrtf(s1[2]);
    float a00 = s1[0] * M[0][0] + WG_EPS;
    float a11 = s1[1] * M[1][1] + WG_EPS;
    float a22 = s1[2] * M[2][2] + WG_EPS;
    float a01 = q0 * q1 * 0.5f * (M[0][1] + M[1][0]);
    float a02 = q0 * q2 * 0.5f * (M[0][2] + M[2][0]);
    float a12 = q1 * q2 * 0.5f * (M[1][2] + M[2][1]);

    // ---- eigenvalues of symmetric 3x3 (trigonometric / Smith method) ----
    float q  = (a00 + a11 + a22) * (1.0f / 3.0f);
    float p1 = a01 * a01 + a02 * a02 + a12 * a12;
    float m0 = a00 - q, m1 = a11 - q, m2 = a22 - q;
    float p2 = m0 * m0 + m1 * m1 + m2 * m2 + 2.0f * p1;

    float sum_sqrt;
    if (p2 <= 1e-24f) {
        sum_sqrt = 3.0f * sqrtf(fmaxf(q, WG_EPS));
    } else {
        float p  = sqrtf(p2 * (1.0f / 6.0f));
        float ip = 1.0f / p;
        float b00 = m0 * ip, b11 = m1 * ip, b22 = m2 * ip;
        float b01 = a01 * ip, b02 = a02 * ip, b12 = a12 * ip;
        float detB = b00 * (b11 * b22 - b12 * b12)
                   - b01 * (b01 * b22 - b12 * b02)
                   + b02 * (b01 * b12 - b11 * b02);
        float r = fminf(fmaxf(0.5f * detB, -1.0f), 1.0f);
        float phi = acosf(r) * (1.0f / 3.0f);
        float tp = 2.0f * p;
        float e1 = q + tp * cosf(phi);                       // largest
        float e3 = q + tp * cosf(phi + 2.0943951023931953f); // smallest
        float e2 = 3.0f * q - e1 - e3;
        sum_sqrt = sqrtf(fmaxf(e1, WG_EPS))
                 + sqrtf(fmaxf(e2, WG_EPS))
                 + sqrtf(fmaxf(e3, WG_EPS));
    }

    // ---- assemble W2 ----
    float cov_w = (s1[0] + s1[1] + s1[2]) + tr_cov2 - 2.0f * sum_sqrt;
    cov_w = fmaxf(cov_w, 0.0f);
    out[b] = sqrtf(fmaxf(loc_diff2 + cov_w, WG_EPS));
}

extern "C" void kernel_launch(void* const* d_in, const int* in_sizes, int n_in,
                              void* d_out, int out_size)
{
    const float* loc1   = (const float*)d_in[0];
    const float* scale1 = (const float*)d_in[1];
    const float* rot1   = (const float*)d_in[2];
    const float* loc2   = (const float*)d_in[3];
    const float* scale2 = (const float*)d_in[4];
    const float* rot2   = (const float*)d_in[5];
    float* out = (float*)d_out;

    int B = in_sizes[0] / 3;
    int blocks = (B + BLK - 1) / BLK;
    wasserstein_gaussian_kernel<<<blocks, BLK>>>(
        loc1, scale1, rot1, loc2, scale2, rot2, out, B);
}

// round 7
// speedup vs baseline: 1.4930x; 1.4930x over previous
#include <cuda_runtime.h>
#include <cuda_bf16.h>

#define WG_EPS 1e-8f
#define BLK 256

__device__ __forceinline__ float ldg_nc(const float* p) {
    float v;
    asm volatile("ld.global.nc.f32 %0, [%1];" : "=f"(v) : "l"(p));
    return v;
}

__global__ __launch_bounds__(BLK) void wasserstein_gaussian_kernel(
    const float* __restrict__ loc1,
    const float* __restrict__ scale1,
    const float* __restrict__ rot1,
    const float* __restrict__ loc2,
    const float* __restrict__ scale2,
    const float* __restrict__ rot2,
    float* __restrict__ out,
    int B)
{
    int b = blockIdx.x * blockDim.x + threadIdx.x;
    if (b >= B) return;

    // ---- issue ALL 30 loads before any compute (forced via volatile asm) ----
    // Each gets its own destination register -> ~30 outstanding LDGs/thread,
    // keeping the DRAM pipe continuously fed.
    float r1[9], r2[9];
#pragma unroll
    for (int i = 0; i < 9; i++) r1[i] = ldg_nc(rot1 + 9 * b + i);
#pragma unroll
    for (int i = 0; i < 9; i++) r2[i] = ldg_nc(rot2 + 9 * b + i);

    float l1[3], l2[3], s1r[3], s2r[3];
#pragma unroll
    for (int i = 0; i < 3; i++) l1[i]  = ldg_nc(loc1 + 3 * b + i);
#pragma unroll
    for (int i = 0; i < 3; i++) l2[i]  = ldg_nc(loc2 + 3 * b + i);
#pragma unroll
    for (int i = 0; i < 3; i++) s1r[i] = ldg_nc(scale1 + 3 * b + i);
#pragma unroll
    for (int i = 0; i < 3; i++) s2r[i] = ldg_nc(scale2 + 3 * b + i);

    float s1[3], s2[3];
#pragma unroll
    for (int i = 0; i < 3; i++) {
        s1[i] = fmaxf(s1r[i], WG_EPS);
        s2[i] = fmaxf(s2r[i], WG_EPS);
    }

    // ---- loc term ----
    float d0 = l1[0] - l2[0], d1 = l1[1] - l2[1], d2 = l1[2] - l2[2];
    float loc_diff2 = d0 * d0 + d1 * d1 + d2 * d2;

    // ---- cov2 = R2 diag(s2) R2^T (6 unique entries) ----
    float cov2[3][3];
#pragma unroll
    for (int i = 0; i < 3; i++) {
#pragma unroll
        for (int k = i; k < 3; k++) {
            float v = r2[3 * i + 0] * s2[0] * r2[3 * k + 0]
                    + r2[3 * i + 1] * s2[1] * r2[3 * k + 1]
                    + r2[3 * i + 2] * s2[2] * r2[3 * k + 2];
            cov2[i][k] = v;
            cov2[k][i] = v;
        }
    }
    float tr_cov2 = cov2[0][0] + cov2[1][1] + cov2[2][2];

    // ---- M = R1^T cov2 R1 ----
    float T[3][3];
#pragma unroll
    for (int j = 0; j < 3; j++)
#pragma unroll
        for (int l = 0; l < 3; l++)
            T[j][l] = cov2[j][0] * r1[0 * 3 + l]
                    + cov2[j][1] * r1[1 * 3 + l]
                    + cov2[j][2] * r1[2 * 3 + l];

    float M[3][3];
#pragma unroll
    for (int i = 0; i < 3; i++)
#pragma unroll
        for (int l = 0; l < 3; l++)
            M[i][l] = r1[0 * 3 + i] * T[0][l]
                    + r1[1 * 3 + i] * T[1][l]
                    + r1[2 * 3 + i] * T[2][l];

    // ---- E = diag(sqrt(s1)) M diag(sqrt(s1)), symmetrized + EPS*I ----
    float q0 = sqrtf(s1[0]), q1 = sqrtf(s1[1]), q2 = sqrtf(s1[2]);
    float a00 = s1[0] * M[0][0] + WG_EPS;
    float a11 = s1[1] * M[1][1] + WG_EPS;
    float a22 = s1[2] * M[2][2] + WG_EPS;
    float a01 = q0 * q1 * 0.5f * (M[0][1] + M[1][0]);
    float a02 = q0 * q2 * 0.5f * (M[0][2] + M[2][0]);
    float a12 = q1 * q2 * 0.5f * (M[1][2] + M[2][1]);

    // ---- eigenvalues of symmetric 3x3 (trigonometric / Smith method) ----
    float q  = (a00 + a11 + a22) * (1.0f / 3.0f);
    float p1 = a01 * a01 + a02 * a02 + a12 * a12;
    float m0 = a00 - q, m1 = a11 - q, m2 = a22 - q;
    float p2 = m0 * m0 + m1 * m1 + m2 * m2 + 2.0f * p1;

    float sum_sqrt;
    if (p2 <= 1e-24f) {
        sum_sqrt = 3.0f * sqrtf(fmaxf(q, WG_EPS));
    } else {
        float p  = sqrtf(p2 * (1.0f / 6.0f));
        float ip = 1.0f / p;
        float b00 = m0 * ip, b11 = m1 * ip, b22 = m2 * ip;
        float b01 = a01 * ip, b02 = a02 * ip, b12 = a12 * ip;
        float detB = b00 * (b11 * b22 - b12 * b12)
                   - b01 * (b01 * b22 - b12 * b02)
                   + b02 * (b01 * b12 - b11 * b02);
        float r = fminf(fmaxf(0.5f * detB, -1.0f), 1.0f);
        float phi = acosf(r) * (1.0f / 3.0f);
        float tp = 2.0f * p;
        float e1 = q + tp * cosf(phi);                       // largest
        float e3 = q + tp * cosf(phi + 2.0943951023931953f); // smallest
        float e2 = 3.0f * q - e1 - e3;
        sum_sqrt = sqrtf(fmaxf(e1, WG_EPS))
                 + sqrtf(fmaxf(e2, WG_EPS))
                 + sqrtf(fmaxf(e3, WG_EPS));
    }

    // ---- assemble W2 ----
    float cov_w = (s1[0] + s1[1] + s1[2]) + tr_cov2 - 2.0f * sum_sqrt;
    cov_w = fmaxf(cov_w, 0.0f);
    out[b] = sqrtf(fmaxf(loc_diff2 + cov_w, WG_EPS));
}

extern "C" void kernel_launch(void* const* d_in, const int* in_sizes, int n_in,
                              void* d_out, int out_size)
{
    const float* loc1   = (const float*)d_in[0];
    const float* scale1 = (const float*)d_in[1];
    const float* rot1   = (const float*)d_in[2];
    const float* loc2   = (const float*)d_in[3];
    const float* scale2 = (const float*)d_in[4];
    const float* rot2   = (const float*)d_in[5];
    float* out = (float*)d_out;

    int B = in_sizes[0] / 3;
    int blocks = (B + BLK - 1) / BLK;
    wasserstein_gaussian_kernel<<<blocks, BLK>>>(
        loc1, scale1, rot1, loc2, scale2, rot2, out, B);
}